// round 1
// baseline (speedup 1.0000x reference)
#include <cuda_runtime.h>

#define BB 1024
#define DD 256
#define HH 32

// Precomputed exp(+W) / exp(-W), transposed to [H, D] for coalesced inner-loop reads.
__device__ float g_ewpT[HH * DD];
__device__ float g_ewmT[HH * DD];

__global__ void precompute_kernel(const float* __restrict__ W) {
    int i = blockIdx.x * blockDim.x + threadIdx.x;
    if (i < DD * HH) {
        int d = i >> 5;       // row in W [D, H]
        int j = i & 31;       // col in W
        float w = W[i];       // W[d*H + j]
        g_ewpT[j * DD + d] = expf(w);
        g_ewmT[j * DD + d] = expf(-w);
    }
}

__global__ __launch_bounds__(256) void gwg_kernel(
    const float* __restrict__ x,
    const float* __restrict__ W,
    const float* __restrict__ b,
    const float* __restrict__ c,
    const float* __restrict__ gum,
    const float* __restrict__ acc,
    float* __restrict__ out)
{
    __shared__ float  xs[DD];
    __shared__ float  ap[8][32];
    __shared__ float2 sC[HH];     // (sigmoid(a_j), sigmoid(-a_j))
    __shared__ float  sE[HH];     // exp(a_j), for the rank-1 update
    __shared__ float  redf[8];
    __shared__ float  redk[8];
    __shared__ int    redi[8];
    __shared__ float  sZf, sZr;
    __shared__ int    sKstar;

    const int row  = blockIdx.x;
    const int tid  = threadIdx.x;
    const int w    = tid >> 5;
    const int lane = tid & 31;
    const int k    = tid;

    float xk = x[row * DD + k];
    xs[k] = xk;
    __syncthreads();

    // ---- a_j = c_j + sum_d x_d W[d,j]  (warp-partial over d, lane = j) ----
    {
        float part = 0.f;
        const int base = w * 32;
        #pragma unroll
        for (int kk = 0; kk < 32; ++kk)
            part = fmaf(xs[base + kk], W[(base + kk) * HH + lane], part);
        ap[w][lane] = part;
    }
    __syncthreads();
    if (tid < HH) {
        float a = c[tid];
        #pragma unroll
        for (int ww = 0; ww < 8; ++ww) a += ap[ww][tid];
        float E   = expf(a);
        float inv = 1.0f / (1.0f + E);
        sE[tid] = E;
        sC[tid] = make_float2(E * inv, inv);   // (sigmoid(a), sigmoid(-a))
    }
    __syncthreads();

    // ---- forward logits: l_k = 0.5*(delta*b_k + log prod_j (EI_j*e^{delta w} + I_j)) ----
    const float bk    = b[k];
    const float delta = 1.f - 2.f * xk;
    const float* ewT  = (xk == 0.0f) ? g_ewpT : g_ewmT;

    float p0 = 1.f, p1 = 1.f, p2 = 1.f, p3 = 1.f;
    #pragma unroll
    for (int j = 0; j < HH; j += 4) {
        float2 c0 = sC[j], c1 = sC[j + 1], c2 = sC[j + 2], c3 = sC[j + 3];
        p0 *= fmaf(c0.x, ewT[(j + 0) * DD + k], c0.y);
        p1 *= fmaf(c1.x, ewT[(j + 1) * DD + k], c1.y);
        p2 *= fmaf(c2.x, ewT[(j + 2) * DD + k], c2.y);
        p3 *= fmaf(c3.x, ewT[(j + 3) * DD + k], c3.y);
    }
    float p  = (p0 * p1) * (p2 * p3);
    float lk = 0.5f * fmaf(delta, bk, logf(p));
    float ek = expf(lk);

    // gumbel key (match reference formula exactly)
    float u   = gum[row * DD + k];
    float g   = -logf(-logf(u + 1e-9f) + 1e-9f);
    float key = lk + g;
    int   ki  = k;

    // ---- warp reduce: sum(ek) and argmax(key) [tie -> lowest index] ----
    float s = ek;
    #pragma unroll
    for (int off = 16; off; off >>= 1) {
        s += __shfl_xor_sync(0xffffffffu, s, off);
        float ov = __shfl_xor_sync(0xffffffffu, key, off);
        int   oi = __shfl_xor_sync(0xffffffffu, ki,  off);
        if (ov > key || (ov == key && oi < ki)) { key = ov; ki = oi; }
    }
    if (lane == 0) { redf[w] = s; redk[w] = key; redi[w] = ki; }
    __syncthreads();
    if (tid == 0) {
        float Z = 0.f, bv = redk[0];
        int   bi = redi[0];
        #pragma unroll
        for (int ww = 0; ww < 8; ++ww) {
            Z += redf[ww];
            if (redk[ww] > bv || (redk[ww] == bv && redi[ww] < bi)) {
                bv = redk[ww]; bi = redi[ww];
            }
        }
        sZf = Z; sKstar = bi;
    }
    __syncthreads();
    const int kstar = sKstar;

    // ---- rank-1 update of sigmoids for the flipped state ----
    if (tid < HH) {
        float xks = xs[kstar];
        const float* ewT2 = (xks == 0.0f) ? g_ewpT : g_ewmT;
        float E2   = sE[tid] * ewT2[tid * DD + kstar];
        float inv2 = 1.0f / (1.0f + E2);
        sC[tid] = make_float2(E2 * inv2, inv2);
    }
    __syncthreads();

    // ---- reverse logits at x_delta ----
    float xk2 = (k == kstar) ? 1.f - xk : xk;
    float d2  = 1.f - 2.f * xk2;
    const float* ewT3 = (xk2 == 0.0f) ? g_ewpT : g_ewmT;

    float q0 = 1.f, q1 = 1.f, q2 = 1.f, q3 = 1.f;
    #pragma unroll
    for (int j = 0; j < HH; j += 4) {
        float2 c0 = sC[j], c1 = sC[j + 1], c2 = sC[j + 2], c3 = sC[j + 3];
        q0 *= fmaf(c0.x, ewT3[(j + 0) * DD + k], c0.y);
        q1 *= fmaf(c1.x, ewT3[(j + 1) * DD + k], c1.y);
        q2 *= fmaf(c2.x, ewT3[(j + 2) * DD + k], c2.y);
        q3 *= fmaf(c3.x, ewT3[(j + 3) * DD + k], c3.y);
    }
    float q   = (q0 * q1) * (q2 * q3);
    float lk2 = 0.5f * fmaf(d2, bk, logf(q));
    float ek2 = expf(lk2);

    float s2 = ek2;
    #pragma unroll
    for (int off = 16; off; off >>= 1)
        s2 += __shfl_xor_sync(0xffffffffu, s2, off);
    if (lane == 0) redf[w] = s2;
    __syncthreads();
    if (tid == 0) {
        float Z = 0.f;
        #pragma unroll
        for (int ww = 0; ww < 8; ++ww) Z += redf[ww];
        sZr = Z;
    }
    __syncthreads();

    // ---- accept / reject, write row ----
    float la   = sZf / sZr;
    bool  accv = la > acc[row];
    float out_k = (k == kstar && accv) ? (1.f - xk) : xk;
    out[row * DD + k] = out_k;
}

extern "C" void kernel_launch(void* const* d_in, const int* in_sizes, int n_in,
                              void* d_out, int out_size) {
    const float* x   = (const float*)d_in[0];
    const float* W   = (const float*)d_in[1];
    const float* b   = (const float*)d_in[2];
    const float* c   = (const float*)d_in[3];
    const float* gum = (const float*)d_in[4];
    const float* acc = (const float*)d_in[5];
    float* out = (float*)d_out;

    precompute_kernel<<<(DD * HH + 255) / 256, 256>>>(W);
    gwg_kernel<<<BB, 256>>>(x, W, b, c, gum, acc, out);
}

// round 2
// speedup vs baseline: 1.0617x; 1.0617x over previous
#include <cuda_runtime.h>

#define BB 1024
#define DD 256
#define HH 32

// exp(+W)/exp(-W), interleaved by j-pair: float2 element [pr*DD + d] holds
// (exp(s*W[d, 2*pr]), exp(s*W[d, 2*pr+1])) -> one coalesced LDG.64 per 2 factors.
__device__ float g_ewp[HH * DD];
__device__ float g_ewm[HH * DD];

__global__ void precompute_kernel(const float* __restrict__ W) {
    int i = blockIdx.x * blockDim.x + threadIdx.x;
    if (i < DD * HH) {
        int d = i >> 5;       // row in W [D, H]
        int j = i & 31;       // col in W
        float w = W[i];
        int idx = (j >> 1) * (DD * 2) + d * 2 + (j & 1);
        g_ewp[idx] = expf(w);
        g_ewm[idx] = expf(-w);
    }
}

__device__ __forceinline__ unsigned fmono(float f) {
    unsigned u = __float_as_uint(f);
    return (u & 0x80000000u) ? ~u : (u | 0x80000000u);
}

__global__ __launch_bounds__(256) void gwg_kernel(
    const float* __restrict__ x,
    const float* __restrict__ W,
    const float* __restrict__ b,
    const float* __restrict__ c,
    const float* __restrict__ gum,
    const float* __restrict__ acc,
    float* __restrict__ out)
{
    __shared__ __align__(16) float  xs[DD];
    __shared__ float  ap[8][32];
    __shared__ __align__(16) float2 sC[HH];   // (sigmoid(a_j), sigmoid(-a_j))
    __shared__ float  sE[HH];                 // exp(a_j)
    __shared__ float  redf[8];
    __shared__ unsigned redk[8];
    __shared__ int    redi[8];
    __shared__ float  sZf, sZr;
    __shared__ int    sKstar;

    const int row  = blockIdx.x;
    const int tid  = threadIdx.x;
    const int w    = tid >> 5;
    const int lane = tid & 31;
    const int k    = tid;

    // hoist all per-row scalars
    float xk = x[row * DD + k];
    float bk = b[k];
    float u  = gum[row * DD + k];
    float au = acc[row];
    xs[k] = xk;
    __syncthreads();

    // ---- a_j = c_j + sum_d x_d W[d,j]  (warp w handles d-chunk, lane = j) ----
    {
        float part = 0.f;
        const int base = w * 32;
        const float4* xv4 = (const float4*)(xs + base);
        #pragma unroll
        for (int q = 0; q < 8; ++q) {
            float4 xv = xv4[q];
            int d = base + q * 4;
            part = fmaf(xv.x, W[(d + 0) * HH + lane], part);
            part = fmaf(xv.y, W[(d + 1) * HH + lane], part);
            part = fmaf(xv.z, W[(d + 2) * HH + lane], part);
            part = fmaf(xv.w, W[(d + 3) * HH + lane], part);
        }
        ap[w][lane] = part;
    }
    __syncthreads();
    if (tid < HH) {
        float a = c[tid];
        #pragma unroll
        for (int ww = 0; ww < 8; ++ww) a += ap[ww][tid];
        float E   = expf(a);
        float inv = 1.0f / (1.0f + E);
        sE[tid] = E;
        sC[tid] = make_float2(E * inv, inv);
    }
    __syncthreads();

    // ---- forward logits: l_k = 0.5*(delta*b_k + log prod_j (EI_j*e^{delta w} + I_j)) ----
    const float  delta = 1.f - 2.f * xk;
    const float2* ewT  = (const float2*)((xk == 0.0f) ? g_ewp : g_ewm);
    const float4* sC4  = (const float4*)sC;

    float p0 = 1.f, p1 = 1.f, p2 = 1.f, p3 = 1.f;
    #pragma unroll
    for (int jp = 0; jp < 16; jp += 2) {
        float4 cA = sC4[jp];
        float4 cB = sC4[jp + 1];
        float2 eA = __ldg(&ewT[jp * DD + k]);
        float2 eB = __ldg(&ewT[(jp + 1) * DD + k]);
        p0 *= fmaf(cA.x, eA.x, cA.y);
        p1 *= fmaf(cA.z, eA.y, cA.w);
        p2 *= fmaf(cB.x, eB.x, cB.y);
        p3 *= fmaf(cB.z, eB.y, cB.w);
    }
    float p  = (p0 * p1) * (p2 * p3);
    float lk = 0.5f * fmaf(delta, bk, logf(p));
    float ek = expf(lk);

    float g   = -logf(-logf(u + 1e-9f) + 1e-9f);
    float key = lk + g;

    // ---- warp reduce: sum(ek), argmax(key) [tie -> lowest k] via redux ----
    float s = ek;
    #pragma unroll
    for (int off = 16; off; off >>= 1) s += __shfl_xor_sync(0xffffffffu, s, off);
    unsigned km   = fmono(key);
    unsigned wmax = __reduce_max_sync(0xffffffffu, km);
    unsigned ball = __ballot_sync(0xffffffffu, km == wmax);
    if (lane == 0) {
        redf[w] = s;
        redk[w] = wmax;
        redi[w] = w * 32 + (__ffs(ball) - 1);
    }
    __syncthreads();
    if (w == 0) {
        float    Z  = (lane < 8) ? redf[lane] : 0.f;
        unsigned kv = (lane < 8) ? redk[lane] : 0u;
        #pragma unroll
        for (int off = 16; off; off >>= 1) Z += __shfl_xor_sync(0xffffffffu, Z, off);
        unsigned mx = __reduce_max_sync(0xffffffffu, kv);
        unsigned bl = __ballot_sync(0xffffffffu, kv == mx);
        int srcw = __ffs(bl) - 1;                 // lowest warp with max -> lowest k
        if (lane == 0) { sZf = Z; sKstar = redi[srcw]; }
    }
    __syncthreads();
    const int kstar = sKstar;

    // ---- rank-1 update of sigmoids for the flipped state ----
    if (tid < HH) {
        float xks = xs[kstar];
        const float2* t2 = (const float2*)((xks == 0.0f) ? g_ewp : g_ewm);
        float2 pr = __ldg(&t2[(tid >> 1) * DD + kstar]);
        float m   = (tid & 1) ? pr.y : pr.x;
        float E2   = sE[tid] * m;
        float inv2 = 1.0f / (1.0f + E2);
        sC[tid] = make_float2(E2 * inv2, inv2);
    }
    __syncthreads();

    // ---- reverse logits at x_delta ----
    float xk2 = (k == kstar) ? 1.f - xk : xk;
    float d2  = 1.f - 2.f * xk2;
    const float2* ewT3 = (const float2*)((xk2 == 0.0f) ? g_ewp : g_ewm);

    float q0 = 1.f, q1 = 1.f, q2 = 1.f, q3 = 1.f;
    #pragma unroll
    for (int jp = 0; jp < 16; jp += 2) {
        float4 cA = sC4[jp];
        float4 cB = sC4[jp + 1];
        float2 eA = __ldg(&ewT3[jp * DD + k]);
        float2 eB = __ldg(&ewT3[(jp + 1) * DD + k]);
        q0 *= fmaf(cA.x, eA.x, cA.y);
        q1 *= fmaf(cA.z, eA.y, cA.w);
        q2 *= fmaf(cB.x, eB.x, cB.y);
        q3 *= fmaf(cB.z, eB.y, cB.w);
    }
    float q   = (q0 * q1) * (q2 * q3);
    float lk2 = 0.5f * fmaf(d2, bk, logf(q));
    float ek2 = expf(lk2);

    float s2 = ek2;
    #pragma unroll
    for (int off = 16; off; off >>= 1) s2 += __shfl_xor_sync(0xffffffffu, s2, off);
    if (lane == 0) redf[w] = s2;
    __syncthreads();
    if (w == 0) {
        float Z = (lane < 8) ? redf[lane] : 0.f;
        #pragma unroll
        for (int off = 16; off; off >>= 1) Z += __shfl_xor_sync(0xffffffffu, Z, off);
        if (lane == 0) sZr = Z;
    }
    __syncthreads();

    // ---- accept / reject, write row ----
    bool  accv  = (sZf / sZr) > au;
    float out_k = (k == kstar && accv) ? (1.f - xk) : xk;
    out[row * DD + k] = out_k;
}

extern "C" void kernel_launch(void* const* d_in, const int* in_sizes, int n_in,
                              void* d_out, int out_size) {
    const float* x   = (const float*)d_in[0];
    const float* W   = (const float*)d_in[1];
    const float* b   = (const float*)d_in[2];
    const float* c   = (const float*)d_in[3];
    const float* gum = (const float*)d_in[4];
    const float* acc = (const float*)d_in[5];
    float* out = (float*)d_out;

    precompute_kernel<<<(DD * HH + 255) / 256, 256>>>(W);
    gwg_kernel<<<BB, 256>>>(x, W, b, c, gum, acc, out);
}